// round 5
// baseline (speedup 1.0000x reference)
#include <cuda_runtime.h>
#include <math.h>

#define GAMMA 0.99f
#define LAM   0.95f
#define GL    (GAMMA * LAM)
#define EPSN  1e-8

#define CHUNKS 64
#define MAXN   8192
#define MAXT   2048
#define TPB    256
#define NSLOT  (CHUNKS * MAXN)
#define RBLK   (NSLOT / TPB)          // 2048 phase2b partial slots

// Static device scratch (no allocations allowed).
__device__ float2   g_CD[NSLOT];                 // {C, D}              4 MB
__device__ float4   g_S4[NSLOT];                 // {S1, SC, S2, SDC}  16 MB
__device__ float    g_SC2[NSLOT];                //                     4 MB
__device__ float    g_carry[NSLOT];              //                     2 MB
__device__ unsigned g_bits[(MAXT * MAXN) / 32];  // done bits           2 MB
__device__ double   g_part[2 * RBLK];
__device__ float    g_mean;
__device__ float    g_inv;   // 1 / (std + eps)

// Bit layout contract (writer = phase1, reader = gae_write, identical thread
// mapping): for a warp covering columns [colbase, colbase+128), word j of the
// uint4 at g_bits[t*(N/32) + colbase/32 + j] has bit l = done(t, colbase+4l+j).

// ---------------------------------------------------------------------------
// Phase 1: per (chunk, 4-column group), compose the reverse recurrence into
// a_out = D + C * a_in, accumulate sufficient statistics for global mean/std,
// and bit-pack dones for the write pass.
// ---------------------------------------------------------------------------
__global__ __launch_bounds__(TPB)
void gae_phase1(const float* __restrict__ rw, const float* __restrict__ val,
                const int* __restrict__ dn, int N, int L) {
    int groups = N >> 2;
    int tid = blockIdx.x * blockDim.x + threadIdx.x;
    if (tid >= CHUNKS * groups) return;
    int c    = tid / groups;
    int g    = tid - c * groups;
    int col  = g << 2;
    int lane = threadIdx.x & 31;
    int colbase  = col - (lane << 2);
    int wordbase = colbase >> 5;
    int nw   = N >> 5;
    int t0   = c * L;
    int t1   = t0 + L - 1;

    float C[4]  = {1.f, 1.f, 1.f, 1.f};
    float D[4]  = {0.f, 0.f, 0.f, 0.f};
    float S1[4] = {0.f, 0.f, 0.f, 0.f};
    float SC[4] = {0.f, 0.f, 0.f, 0.f};
    float S2[4] = {0.f, 0.f, 0.f, 0.f};
    float SDC[4]= {0.f, 0.f, 0.f, 0.f};
    float SC2[4]= {0.f, 0.f, 0.f, 0.f};

    float4 vn = *reinterpret_cast<const float4*>(val + (size_t)(t1 + 1) * N + col);
    #pragma unroll 4
    for (int t = t1; t >= t0; --t) {
        float4 r  = *reinterpret_cast<const float4*>(rw + (size_t)t * N + col);
        int4   dd = *reinterpret_cast<const int4*>(dn + (size_t)t * N + col);
        float4 vc = *reinterpret_cast<const float4*>(val + (size_t)t * N + col);

        unsigned b0 = __ballot_sync(0xFFFFFFFFu, dd.x != 0);
        unsigned b1 = __ballot_sync(0xFFFFFFFFu, dd.y != 0);
        unsigned b2 = __ballot_sync(0xFFFFFFFFu, dd.z != 0);
        unsigned b3 = __ballot_sync(0xFFFFFFFFu, dd.w != 0);
        if (lane == 0)
            *reinterpret_cast<uint4*>(g_bits + (size_t)t * nw + wordbase) =
                make_uint4(b0, b1, b2, b3);

        float rr[4] = {r.x, r.y, r.z, r.w};
        float vv[4] = {vc.x, vc.y, vc.z, vc.w};
        float vnn[4]= {vn.x, vn.y, vn.z, vn.w};
        int   di[4] = {dd.x, dd.y, dd.z, dd.w};

        #pragma unroll
        for (int j = 0; j < 4; ++j) {
            float nt  = di[j] ? 0.f : 1.f;
            float del = fmaf(GAMMA * nt, vnn[j], rr[j]) - vv[j];
            float cf  = GL * nt;
            D[j] = fmaf(cf, D[j], del);
            C[j] *= cf;
            S1[j] += D[j];
            SC[j] += C[j];
            S2[j]  = fmaf(D[j], D[j], S2[j]);
            SDC[j] = fmaf(D[j], C[j], SDC[j]);
            SC2[j] = fmaf(C[j], C[j], SC2[j]);
        }
        vn = vc;
    }
    size_t o = (size_t)c * N + col;
    #pragma unroll
    for (int j = 0; j < 4; ++j) {
        g_CD [o + j] = make_float2(C[j], D[j]);
        g_S4 [o + j] = make_float4(S1[j], SC[j], S2[j], SDC[j]);
        g_SC2[o + j] = SC2[j];
    }
}

// ---------------------------------------------------------------------------
// Phase 2a (scan): one thread per column, reverse-scan ONLY {C,D} (4 MB) to
// produce the carry entering each chunk. Slim on purpose — this kernel has
// just 32 blocks, so keep its traffic tiny.
// ---------------------------------------------------------------------------
__global__ __launch_bounds__(TPB)
void gae_scan(int N) {
    int col = blockIdx.x * blockDim.x + threadIdx.x;
    if (col >= N) return;
    float a = 0.f;
    #pragma unroll 16
    for (int c = CHUNKS - 1; c >= 0; --c) {
        size_t o = (size_t)c * N + col;
        g_carry[o] = a;
        float2 cd = g_CD[o];
        a = fmaf(cd.x, a, cd.y);
    }
}

// ---------------------------------------------------------------------------
// Phase 2b (stats): one thread per (chunk, column) — 2048 blocks, full-BW read
// of the 24 MB of stats. Closed forms:
//   sum_chunk   = S1 + SC*a ;  sumsq_chunk = S2 + 2*SDC*a + SC2*a*a
// Deterministic per-block reduction into g_part.
// ---------------------------------------------------------------------------
__global__ __launch_bounds__(TPB)
void gae_stats(int total) {
    int i = blockIdx.x * blockDim.x + threadIdx.x;
    float ts = 0.f, ts2 = 0.f;
    if (i < total) {
        float4 S   = g_S4[i];
        float  sc2 = g_SC2[i];
        float  a   = g_carry[i];
        ts  = fmaf(S.y, a, S.x);
        ts2 = fmaf(fmaf(sc2, a, 2.f * S.w), a, S.z);
    }
    __shared__ double ss[TPB];
    __shared__ double ss2[TPB];
    ss[threadIdx.x]  = (double)ts;
    ss2[threadIdx.x] = (double)ts2;
    __syncthreads();
    for (int st = TPB / 2; st > 0; st >>= 1) {
        if (threadIdx.x < st) {
            ss[threadIdx.x]  += ss[threadIdx.x + st];
            ss2[threadIdx.x] += ss2[threadIdx.x + st];
        }
        __syncthreads();
    }
    if (threadIdx.x == 0) {
        g_part[2 * blockIdx.x]     = ss[0];
        g_part[2 * blockIdx.x + 1] = ss2[0];
    }
}

// ---------------------------------------------------------------------------
// Finalize stats: single block -> mean, 1/(std+eps), ddof=1.
// ---------------------------------------------------------------------------
__global__ void gae_finalize(int nblocks, long long M) {
    __shared__ double ss[TPB];
    __shared__ double ss2[TPB];
    double s = 0.0, s2 = 0.0;
    for (int i = threadIdx.x; i < nblocks; i += TPB) {
        s  += g_part[2 * i];
        s2 += g_part[2 * i + 1];
    }
    ss[threadIdx.x]  = s;
    ss2[threadIdx.x] = s2;
    __syncthreads();
    for (int st = TPB / 2; st > 0; st >>= 1) {
        if (threadIdx.x < st) {
            ss[threadIdx.x]  += ss[threadIdx.x + st];
            ss2[threadIdx.x] += ss2[threadIdx.x + st];
        }
        __syncthreads();
    }
    if (threadIdx.x == 0) {
        double mean = ss[0] / (double)M;
        double var  = (ss2[0] - ss[0] * ss[0] / (double)M) / (double)(M - 1);
        if (var < 0.0) var = 0.0;
        g_mean = (float)mean;
        g_inv  = (float)(1.0 / (sqrt(var) + EPSN));
    }
}

// ---------------------------------------------------------------------------
// Write pass: replay recurrence with correct carry; dones come from the 2 MB
// bitmask (one broadcast LDG.128 per warp per t). Plain loads/stores — the
// round-1 idiom that achieved 6.5 TB/s effective.
// ---------------------------------------------------------------------------
__global__ __launch_bounds__(TPB)
void gae_write(const float* __restrict__ rw, const float* __restrict__ val,
               float* __restrict__ adv, float* __restrict__ ret,
               int N, int L) {
    int groups = N >> 2;
    int tid = blockIdx.x * blockDim.x + threadIdx.x;
    if (tid >= CHUNKS * groups) return;
    int c    = tid / groups;
    int g    = tid - c * groups;
    int col  = g << 2;
    int lane = threadIdx.x & 31;
    int colbase  = col - (lane << 2);
    int wordbase = colbase >> 5;
    int nw   = N >> 5;
    int t0   = c * L;
    int t1   = t0 + L - 1;

    float m   = g_mean;
    float inv = g_inv;

    float4 a  = *reinterpret_cast<const float4*>(g_carry + (size_t)c * N + col);
    float4 vn = *reinterpret_cast<const float4*>(val + (size_t)(t1 + 1) * N + col);

    #pragma unroll 4
    for (int t = t1; t >= t0; --t) {
        float4 r  = *reinterpret_cast<const float4*>(rw + (size_t)t * N + col);
        float4 vc = *reinterpret_cast<const float4*>(val + (size_t)t * N + col);
        uint4  bw = *reinterpret_cast<const uint4*>(g_bits + (size_t)t * nw + wordbase);

        float nt0 = ((bw.x >> lane) & 1u) ? 0.f : 1.f;
        float nt1 = ((bw.y >> lane) & 1u) ? 0.f : 1.f;
        float nt2 = ((bw.z >> lane) & 1u) ? 0.f : 1.f;
        float nt3 = ((bw.w >> lane) & 1u) ? 0.f : 1.f;

        a.x = fmaf(GL * nt0, a.x, fmaf(GAMMA * nt0, vn.x, r.x) - vc.x);
        a.y = fmaf(GL * nt1, a.y, fmaf(GAMMA * nt1, vn.y, r.y) - vc.y);
        a.z = fmaf(GL * nt2, a.z, fmaf(GAMMA * nt2, vn.z, r.z) - vc.z);
        a.w = fmaf(GL * nt3, a.w, fmaf(GAMMA * nt3, vn.w, r.w) - vc.w);

        size_t o = (size_t)t * N + col;
        *reinterpret_cast<float4*>(adv + o) =
            make_float4((a.x - m) * inv, (a.y - m) * inv,
                        (a.z - m) * inv, (a.w - m) * inv);
        *reinterpret_cast<float4*>(ret + o) =
            make_float4(a.x + vc.x, a.y + vc.y, a.z + vc.z, a.w + vc.w);

        vn = vc;
    }
}

extern "C" void kernel_launch(void* const* d_in, const int* in_sizes, int n_in,
                              void* d_out, int out_size) {
    const float* rw  = (const float*)d_in[0];   // rewards [T, N]
    const float* val = (const float*)d_in[1];   // values  [T+1, N]
    const int*   dn  = (const int*)d_in[2];     // dones   [T, N]
    float* out = (float*)d_out;                 // [adv_norm TN | returns TN]

    int TN = in_sizes[0];
    int N  = in_sizes[1] - in_sizes[0];
    int T  = TN / N;
    int L  = T / CHUNKS;

    int groups  = N >> 2;
    int nth     = CHUNKS * groups;
    int blocks1 = (nth + TPB - 1) / TPB;
    int total   = CHUNKS * N;
    int blocksS = (total + TPB - 1) / TPB;

    float* adv = out;
    float* ret = out + (size_t)TN;

    gae_phase1<<<blocks1, TPB>>>(rw, val, dn, N, L);
    gae_scan<<<(N + TPB - 1) / TPB, TPB>>>(N);
    gae_stats<<<blocksS, TPB>>>(total);
    gae_finalize<<<1, TPB>>>(blocksS, (long long)TN);
    gae_write<<<blocks1, TPB>>>(rw, val, adv, ret, N, L);
}

// round 6
// speedup vs baseline: 1.0231x; 1.0231x over previous
#include <cuda_runtime.h>
#include <math.h>

#define GAMMA 0.99f
#define LAM   0.95f
#define GL    (GAMMA * LAM)
#define EPSN  1e-8

#define CHUNKS 64
#define MAXN   8192
#define MAXT   2048
#define TPB    256
#define NSLOT  (CHUNKS * MAXN)
#define RBLK   (NSLOT / TPB)          // 2048 stats partial slots

// Static device scratch (no allocations allowed).
__device__ float2        g_CD[NSLOT];               // {C, D}              4 MB
__device__ float4        g_S4[NSLOT];               // {S1, SC, S2, SDC}  16 MB
__device__ float         g_SC2[NSLOT];              //                     4 MB
__device__ float         g_carry[NSLOT];            //                     2 MB
__device__ unsigned char g_dbyte[(MAXT * MAXN) / 4];// done bytes          4 MB
__device__ double        g_part[2 * RBLK];
__device__ float         g_mean;
__device__ float         g_inv;   // 1 / (std + eps)

// Done-byte contract: thread handling columns [4g, 4g+4) at time t writes
// g_dbyte[t*(N/4) + g], bit j = done(t, 4g+j). Same thread mapping in both
// phase1 (writer) and gae_write (reader); per-thread, no warp sync involved.

// ---------------------------------------------------------------------------
// Phase 1: per (chunk, 4-column group), compose the reverse recurrence into
// a_out = D + C * a_in, accumulate sufficient statistics for global mean/std,
// and pack this thread's 4 done flags into one byte per t (coalesced, ALU-only).
// ---------------------------------------------------------------------------
__global__ __launch_bounds__(TPB)
void gae_phase1(const float* __restrict__ rw, const float* __restrict__ val,
                const int* __restrict__ dn, int N, int L) {
    int groups = N >> 2;
    int tid = blockIdx.x * blockDim.x + threadIdx.x;
    if (tid >= CHUNKS * groups) return;
    int c   = tid / groups;
    int g   = tid - c * groups;
    int col = g << 2;
    int t0  = c * L;
    int t1  = t0 + L - 1;

    float C[4]  = {1.f, 1.f, 1.f, 1.f};
    float D[4]  = {0.f, 0.f, 0.f, 0.f};
    float S1[4] = {0.f, 0.f, 0.f, 0.f};
    float SC[4] = {0.f, 0.f, 0.f, 0.f};
    float S2[4] = {0.f, 0.f, 0.f, 0.f};
    float SDC[4]= {0.f, 0.f, 0.f, 0.f};
    float SC2[4]= {0.f, 0.f, 0.f, 0.f};

    float4 vn = *reinterpret_cast<const float4*>(val + (size_t)(t1 + 1) * N + col);
    #pragma unroll 4
    for (int t = t1; t >= t0; --t) {
        float4 r  = *reinterpret_cast<const float4*>(rw + (size_t)t * N + col);
        int4   dd = *reinterpret_cast<const int4*>(dn + (size_t)t * N + col);
        float4 vc = *reinterpret_cast<const float4*>(val + (size_t)t * N + col);

        unsigned mb = (dd.x ? 1u : 0u) | (dd.y ? 2u : 0u) |
                      (dd.z ? 4u : 0u) | (dd.w ? 8u : 0u);
        g_dbyte[(size_t)t * groups + g] = (unsigned char)mb;

        float rr[4] = {r.x, r.y, r.z, r.w};
        float vv[4] = {vc.x, vc.y, vc.z, vc.w};
        float vnn[4]= {vn.x, vn.y, vn.z, vn.w};
        int   di[4] = {dd.x, dd.y, dd.z, dd.w};

        #pragma unroll
        for (int j = 0; j < 4; ++j) {
            float nt  = di[j] ? 0.f : 1.f;
            float del = fmaf(GAMMA * nt, vnn[j], rr[j]) - vv[j];
            float cf  = GL * nt;
            D[j] = fmaf(cf, D[j], del);
            C[j] *= cf;
            S1[j] += D[j];
            SC[j] += C[j];
            S2[j]  = fmaf(D[j], D[j], S2[j]);
            SDC[j] = fmaf(D[j], C[j], SDC[j]);
            SC2[j] = fmaf(C[j], C[j], SC2[j]);
        }
        vn = vc;
    }
    size_t o = (size_t)c * N + col;
    #pragma unroll
    for (int j = 0; j < 4; ++j) {
        g_CD [o + j] = make_float2(C[j], D[j]);
        g_S4 [o + j] = make_float4(S1[j], SC[j], S2[j], SDC[j]);
        g_SC2[o + j] = SC2[j];
    }
}

// ---------------------------------------------------------------------------
// Phase 2a (scan): one thread per column, reverse-scan ONLY {C,D} (4 MB) to
// produce the carry entering each chunk. Slim because it has just 32 blocks.
// ---------------------------------------------------------------------------
__global__ __launch_bounds__(TPB)
void gae_scan(int N) {
    int col = blockIdx.x * blockDim.x + threadIdx.x;
    if (col >= N) return;
    float a = 0.f;
    #pragma unroll 16
    for (int c = CHUNKS - 1; c >= 0; --c) {
        size_t o = (size_t)c * N + col;
        g_carry[o] = a;
        float2 cd = g_CD[o];
        a = fmaf(cd.x, a, cd.y);
    }
}

// ---------------------------------------------------------------------------
// Phase 2b (stats): one thread per (chunk, column), full-BW read of the stats.
//   sum_chunk   = S1 + SC*a ;  sumsq_chunk = S2 + 2*SDC*a + SC2*a*a
// ---------------------------------------------------------------------------
__global__ __launch_bounds__(TPB)
void gae_stats(int total) {
    int i = blockIdx.x * blockDim.x + threadIdx.x;
    float ts = 0.f, ts2 = 0.f;
    if (i < total) {
        float4 S   = g_S4[i];
        float  sc2 = g_SC2[i];
        float  a   = g_carry[i];
        ts  = fmaf(S.y, a, S.x);
        ts2 = fmaf(fmaf(sc2, a, 2.f * S.w), a, S.z);
    }
    __shared__ double ss[TPB];
    __shared__ double ss2[TPB];
    ss[threadIdx.x]  = (double)ts;
    ss2[threadIdx.x] = (double)ts2;
    __syncthreads();
    for (int st = TPB / 2; st > 0; st >>= 1) {
        if (threadIdx.x < st) {
            ss[threadIdx.x]  += ss[threadIdx.x + st];
            ss2[threadIdx.x] += ss2[threadIdx.x + st];
        }
        __syncthreads();
    }
    if (threadIdx.x == 0) {
        g_part[2 * blockIdx.x]     = ss[0];
        g_part[2 * blockIdx.x + 1] = ss2[0];
    }
}

// ---------------------------------------------------------------------------
// Finalize stats: single block -> mean, 1/(std+eps), ddof=1.
// ---------------------------------------------------------------------------
__global__ void gae_finalize(int nblocks, long long M) {
    __shared__ double ss[TPB];
    __shared__ double ss2[TPB];
    double s = 0.0, s2 = 0.0;
    for (int i = threadIdx.x; i < nblocks; i += TPB) {
        s  += g_part[2 * i];
        s2 += g_part[2 * i + 1];
    }
    ss[threadIdx.x]  = s;
    ss2[threadIdx.x] = s2;
    __syncthreads();
    for (int st = TPB / 2; st > 0; st >>= 1) {
        if (threadIdx.x < st) {
            ss[threadIdx.x]  += ss[threadIdx.x + st];
            ss2[threadIdx.x] += ss2[threadIdx.x + st];
        }
        __syncthreads();
    }
    if (threadIdx.x == 0) {
        double mean = ss[0] / (double)M;
        double var  = (ss2[0] - ss[0] * ss[0] / (double)M) / (double)(M - 1);
        if (var < 0.0) var = 0.0;
        g_mean = (float)mean;
        g_inv  = (float)(1.0 / (sqrt(var) + EPSN));
    }
}

// ---------------------------------------------------------------------------
// Write pass: replay recurrence with correct carry; dones come from the 4 MB
// byte mask (one coalesced uchar per thread per t instead of 16 bytes of int4).
// Round-2 memory idiom otherwise (plain LDG/STG.128, unroll 4).
// ---------------------------------------------------------------------------
__global__ __launch_bounds__(TPB)
void gae_write(const float* __restrict__ rw, const float* __restrict__ val,
               float* __restrict__ adv, float* __restrict__ ret,
               int N, int L) {
    int groups = N >> 2;
    int tid = blockIdx.x * blockDim.x + threadIdx.x;
    if (tid >= CHUNKS * groups) return;
    int c   = tid / groups;
    int g   = tid - c * groups;
    int col = g << 2;
    int t0  = c * L;
    int t1  = t0 + L - 1;

    float m   = g_mean;
    float inv = g_inv;

    float4 a  = *reinterpret_cast<const float4*>(g_carry + (size_t)c * N + col);
    float4 vn = *reinterpret_cast<const float4*>(val + (size_t)(t1 + 1) * N + col);

    #pragma unroll 4
    for (int t = t1; t >= t0; --t) {
        float4   r  = *reinterpret_cast<const float4*>(rw + (size_t)t * N + col);
        float4   vc = *reinterpret_cast<const float4*>(val + (size_t)t * N + col);
        unsigned mb = (unsigned)g_dbyte[(size_t)t * groups + g];

        float nt0 = (mb & 1u) ? 0.f : 1.f;
        float nt1 = (mb & 2u) ? 0.f : 1.f;
        float nt2 = (mb & 4u) ? 0.f : 1.f;
        float nt3 = (mb & 8u) ? 0.f : 1.f;

        a.x = fmaf(GL * nt0, a.x, fmaf(GAMMA * nt0, vn.x, r.x) - vc.x);
        a.y = fmaf(GL * nt1, a.y, fmaf(GAMMA * nt1, vn.y, r.y) - vc.y);
        a.z = fmaf(GL * nt2, a.z, fmaf(GAMMA * nt2, vn.z, r.z) - vc.z);
        a.w = fmaf(GL * nt3, a.w, fmaf(GAMMA * nt3, vn.w, r.w) - vc.w);

        size_t o = (size_t)t * N + col;
        *reinterpret_cast<float4*>(adv + o) =
            make_float4((a.x - m) * inv, (a.y - m) * inv,
                        (a.z - m) * inv, (a.w - m) * inv);
        *reinterpret_cast<float4*>(ret + o) =
            make_float4(a.x + vc.x, a.y + vc.y, a.z + vc.z, a.w + vc.w);

        vn = vc;
    }
}

extern "C" void kernel_launch(void* const* d_in, const int* in_sizes, int n_in,
                              void* d_out, int out_size) {
    const float* rw  = (const float*)d_in[0];   // rewards [T, N]
    const float* val = (const float*)d_in[1];   // values  [T+1, N]
    const int*   dn  = (const int*)d_in[2];     // dones   [T, N]
    float* out = (float*)d_out;                 // [adv_norm TN | returns TN]

    int TN = in_sizes[0];
    int N  = in_sizes[1] - in_sizes[0];
    int T  = TN / N;
    int L  = T / CHUNKS;

    int groups  = N >> 2;
    int nth     = CHUNKS * groups;
    int blocks1 = (nth + TPB - 1) / TPB;
    int total   = CHUNKS * N;
    int blocksS = (total + TPB - 1) / TPB;

    float* adv = out;
    float* ret = out + (size_t)TN;

    gae_phase1<<<blocks1, TPB>>>(rw, val, dn, N, L);
    gae_scan<<<(N + TPB - 1) / TPB, TPB>>>(N);
    gae_stats<<<blocksS, TPB>>>(total);
    gae_finalize<<<1, TPB>>>(blocksS, (long long)TN);
    gae_write<<<blocks1, TPB>>>(rw, val, adv, ret, N, L);
}

// round 7
// speedup vs baseline: 1.2909x; 1.2618x over previous
#include <cuda_runtime.h>
#include <math.h>

#define GAMMA 0.99f
#define LAM   0.95f
#define GL    (GAMMA * LAM)
#define EPSN  1e-8

#define CHUNKS 64
#define MAXN   8192
#define TPB    256
#define TPB2   64                       // phase2 block size: spread 8192 threads over 128 blocks
#define P2BLK  (MAXN / TPB2)            // 128 partial slots

// Static device scratch (no allocations allowed).
__device__ float4 g_P[CHUNKS * MAXN];   // {C, D, S1, SC}    8 MB
__device__ float4 g_Q[CHUNKS * MAXN];   // {S2, SDC, SC2,_}  8 MB
__device__ float  g_carry[CHUNKS * MAXN];
__device__ double g_part[2 * P2BLK];
__device__ unsigned int g_done_ctr;     // zero-initialized; self-resets each call
__device__ float  g_mean;
__device__ float  g_inv;                // 1 / (std + eps)

// ---------------------------------------------------------------------------
// Phase 1: per (chunk, 4-column group), compose the reverse recurrence into
// a_out = D + C * a_in and accumulate sufficient statistics so the global
// mean/std can be computed from chunk summaries alone. (Identical to the
// measured-117us version.)
// ---------------------------------------------------------------------------
__global__ __launch_bounds__(TPB)
void gae_phase1(const float* __restrict__ rw, const float* __restrict__ val,
                const int* __restrict__ dn, int N, int L) {
    int groups = N >> 2;
    int tid = blockIdx.x * blockDim.x + threadIdx.x;
    if (tid >= CHUNKS * groups) return;
    int c   = tid / groups;
    int g   = tid - c * groups;
    int col = g << 2;
    int t0  = c * L;
    int t1  = t0 + L - 1;

    float C[4]  = {1.f, 1.f, 1.f, 1.f};
    float D[4]  = {0.f, 0.f, 0.f, 0.f};
    float S1[4] = {0.f, 0.f, 0.f, 0.f};
    float SC[4] = {0.f, 0.f, 0.f, 0.f};
    float S2[4] = {0.f, 0.f, 0.f, 0.f};
    float SDC[4]= {0.f, 0.f, 0.f, 0.f};
    float SC2[4]= {0.f, 0.f, 0.f, 0.f};

    float4 vn = *reinterpret_cast<const float4*>(val + (size_t)(t1 + 1) * N + col);
    #pragma unroll 4
    for (int t = t1; t >= t0; --t) {
        float4 r  = *reinterpret_cast<const float4*>(rw + (size_t)t * N + col);
        int4   dd = *reinterpret_cast<const int4*>(dn + (size_t)t * N + col);
        float4 vc = *reinterpret_cast<const float4*>(val + (size_t)t * N + col);

        float rr[4] = {r.x, r.y, r.z, r.w};
        float vv[4] = {vc.x, vc.y, vc.z, vc.w};
        float vnn[4]= {vn.x, vn.y, vn.z, vn.w};
        int   di[4] = {dd.x, dd.y, dd.z, dd.w};

        #pragma unroll
        for (int j = 0; j < 4; ++j) {
            float nt  = di[j] ? 0.f : 1.f;
            float del = fmaf(GAMMA * nt, vnn[j], rr[j]) - vv[j];
            float cf  = GL * nt;
            D[j] = fmaf(cf, D[j], del);
            C[j] *= cf;
            S1[j] += D[j];
            SC[j] += C[j];
            S2[j]  = fmaf(D[j], D[j], S2[j]);
            SDC[j] = fmaf(D[j], C[j], SDC[j]);
            SC2[j] = fmaf(C[j], C[j], SC2[j]);
        }
        vn = vc;
    }
    size_t o = (size_t)c * N + col;
    #pragma unroll
    for (int j = 0; j < 4; ++j) {
        g_P[o + j] = make_float4(C[j], D[j], S1[j], SC[j]);
        g_Q[o + j] = make_float4(S2[j], SDC[j], SC2[j], 0.f);
    }
}

// ---------------------------------------------------------------------------
// Phase 2 (+fused finalize): one thread per column, TPB2=64 so the 8192
// threads land on 128 blocks (~all SMs) instead of 32. Reverse-scan the chunk
// summaries producing carries + column sum/sumsq via closed forms:
//   sum_chunk   = S1 + SC*a ;  sumsq_chunk = S2 + 2*SDC*a + SC2*a*a
// The last block to finish reduces all partials -> g_mean, g_inv (ddof=1).
// Deterministic: partial slots are fixed, one block reduces in fixed order.
// ---------------------------------------------------------------------------
__global__ __launch_bounds__(TPB2)
void gae_phase2(int N, long long M) {
    int col = blockIdx.x * blockDim.x + threadIdx.x;
    float ts = 0.f, ts2 = 0.f;
    if (col < N) {
        float a = 0.f;
        #pragma unroll 8
        for (int c = CHUNKS - 1; c >= 0; --c) {
            size_t o = (size_t)c * N + col;
            g_carry[o] = a;
            float4 P = g_P[o];
            float4 Q = g_Q[o];
            ts  += fmaf(P.w, a, P.z);
            ts2 += fmaf(fmaf(Q.z, a, 2.f * Q.y), a, Q.x);
            a = fmaf(P.x, a, P.y);
        }
    }
    __shared__ double ss[TPB2];
    __shared__ double ss2[TPB2];
    ss[threadIdx.x]  = (double)ts;
    ss2[threadIdx.x] = (double)ts2;
    __syncthreads();
    for (int st = TPB2 / 2; st > 0; st >>= 1) {
        if (threadIdx.x < st) {
            ss[threadIdx.x]  += ss[threadIdx.x + st];
            ss2[threadIdx.x] += ss2[threadIdx.x + st];
        }
        __syncthreads();
    }
    __shared__ bool s_last;
    if (threadIdx.x == 0) {
        g_part[2 * blockIdx.x]     = ss[0];
        g_part[2 * blockIdx.x + 1] = ss2[0];
        __threadfence();
        unsigned int done = atomicAdd(&g_done_ctr, 1u);
        s_last = (done == (unsigned int)gridDim.x - 1u);
    }
    __syncthreads();
    if (s_last) {
        double s = 0.0, s2 = 0.0;
        for (int i = threadIdx.x; i < (int)gridDim.x; i += TPB2) {
            s  += g_part[2 * i];
            s2 += g_part[2 * i + 1];
        }
        ss[threadIdx.x]  = s;
        ss2[threadIdx.x] = s2;
        __syncthreads();
        for (int st = TPB2 / 2; st > 0; st >>= 1) {
            if (threadIdx.x < st) {
                ss[threadIdx.x]  += ss[threadIdx.x + st];
                ss2[threadIdx.x] += ss2[threadIdx.x + st];
            }
            __syncthreads();
        }
        if (threadIdx.x == 0) {
            double mean = ss[0] / (double)M;
            double var  = (ss2[0] - ss[0] * ss[0] / (double)M) / (double)(M - 1);
            if (var < 0.0) var = 0.0;
            g_mean = (float)mean;
            g_inv  = (float)(1.0 / (sqrt(var) + EPSN));
            g_done_ctr = 0u;   // reset for the next graph replay
        }
    }
}

// ---------------------------------------------------------------------------
// Write pass: replay recurrence with correct carry; emit NORMALIZED advantages
// and returns directly. (Identical to the measured-117us version.)
// ---------------------------------------------------------------------------
__global__ __launch_bounds__(TPB)
void gae_write(const float* __restrict__ rw, const float* __restrict__ val,
               const int* __restrict__ dn, float* __restrict__ adv,
               float* __restrict__ ret, int N, int L) {
    int groups = N >> 2;
    int tid = blockIdx.x * blockDim.x + threadIdx.x;
    if (tid >= CHUNKS * groups) return;
    int c   = tid / groups;
    int g   = tid - c * groups;
    int col = g << 2;
    int t0  = c * L;
    int t1  = t0 + L - 1;

    float m   = g_mean;
    float inv = g_inv;

    float4 a  = *reinterpret_cast<const float4*>(g_carry + (size_t)c * N + col);
    float4 vn = *reinterpret_cast<const float4*>(val + (size_t)(t1 + 1) * N + col);

    #pragma unroll 4
    for (int t = t1; t >= t0; --t) {
        float4 r  = *reinterpret_cast<const float4*>(rw + (size_t)t * N + col);
        int4   dd = *reinterpret_cast<const int4*>(dn + (size_t)t * N + col);
        float4 vc = *reinterpret_cast<const float4*>(val + (size_t)t * N + col);

        float nt, del;
        nt = dd.x ? 0.f : 1.f; del = fmaf(GAMMA * nt, vn.x, r.x) - vc.x;
        a.x = fmaf(GL * nt, a.x, del);
        nt = dd.y ? 0.f : 1.f; del = fmaf(GAMMA * nt, vn.y, r.y) - vc.y;
        a.y = fmaf(GL * nt, a.y, del);
        nt = dd.z ? 0.f : 1.f; del = fmaf(GAMMA * nt, vn.z, r.z) - vc.z;
        a.z = fmaf(GL * nt, a.z, del);
        nt = dd.w ? 0.f : 1.f; del = fmaf(GAMMA * nt, vn.w, r.w) - vc.w;
        a.w = fmaf(GL * nt, a.w, del);

        size_t o = (size_t)t * N + col;
        *reinterpret_cast<float4*>(adv + o) =
            make_float4((a.x - m) * inv, (a.y - m) * inv,
                        (a.z - m) * inv, (a.w - m) * inv);
        *reinterpret_cast<float4*>(ret + o) =
            make_float4(a.x + vc.x, a.y + vc.y, a.z + vc.z, a.w + vc.w);

        vn = vc;
    }
}

extern "C" void kernel_launch(void* const* d_in, const int* in_sizes, int n_in,
                              void* d_out, int out_size) {
    const float* rw  = (const float*)d_in[0];   // rewards [T, N]
    const float* val = (const float*)d_in[1];   // values  [T+1, N]
    const int*   dn  = (const int*)d_in[2];     // dones   [T, N]
    float* out = (float*)d_out;                 // [adv_norm TN | returns TN]

    int TN = in_sizes[0];
    int N  = in_sizes[1] - in_sizes[0];
    int T  = TN / N;
    int L  = T / CHUNKS;

    int groups  = N >> 2;
    int nth     = CHUNKS * groups;
    int blocks1 = (nth + TPB - 1) / TPB;
    int blocks2 = (N + TPB2 - 1) / TPB2;

    float* adv = out;
    float* ret = out + (size_t)TN;

    gae_phase1<<<blocks1, TPB>>>(rw, val, dn, N, L);
    gae_phase2<<<blocks2, TPB2>>>(N, (long long)TN);
    gae_write<<<blocks1, TPB>>>(rw, val, dn, adv, ret, N, L);
}